// round 12
// baseline (speedup 1.0000x reference)
#include <cuda_runtime.h>
#include <cuda_bf16.h>
#include <cstdint>

#define BATCH 2
#define SEQ   2048
#define DIM   1024
#define HEADS 16
#define DHEAD 64
#define LATENT 256
#define ROWS  (BATCH*SEQ)
#define QSCALE 0.125f
#define LOG2E  1.44269504088896f
#define EXP_OFF2 8.65617024533378f   /* 6.0 * log2(e) */
#define QLD  1280
#define KVLD 2048

typedef __nv_bfloat16 bf16;

#define SWZ(x) ((uint32_t)(x) ^ ((((uint32_t)(x)) >> 3) & 0x70))

__device__ __forceinline__ uint32_t smem_u32(const void* p) {
    uint32_t a;
    asm("{ .reg .u64 t; cvta.to.shared.u64 t, %1; cvt.u32.u64 %0, t; }" : "=r"(a) : "l"(p));
    return a;
}
__device__ __forceinline__ void cpa16(uint32_t d, const void* s) {
    asm volatile("cp.async.cg.shared.global [%0], [%1], 16;" :: "r"(d), "l"(s));
}
#define CPA_COMMIT() asm volatile("cp.async.commit_group;" ::: "memory")
#define CPA_WAIT0()  asm volatile("cp.async.wait_group 0;" ::: "memory")
#define CPA_WAIT1()  asm volatile("cp.async.wait_group 1;" ::: "memory")

__device__ __forceinline__ void ldsm4(uint32_t a, uint32_t& r0, uint32_t& r1, uint32_t& r2, uint32_t& r3) {
    asm volatile("ldmatrix.sync.aligned.m8n8.x4.shared.b16 {%0,%1,%2,%3}, [%4];"
                 : "=r"(r0), "=r"(r1), "=r"(r2), "=r"(r3) : "r"(a));
}
__device__ __forceinline__ void hmma(float* c, const uint32_t* a, uint32_t b0, uint32_t b1) {
    asm volatile("mma.sync.aligned.m16n8k16.row.col.f32.bf16.bf16.f32 "
        "{%0,%1,%2,%3}, {%4,%5,%6,%7}, {%8,%9}, {%0,%1,%2,%3};"
        : "+f"(c[0]), "+f"(c[1]), "+f"(c[2]), "+f"(c[3])
        : "r"(a[0]), "r"(a[1]), "r"(a[2]), "r"(a[3]), "r"(b0), "r"(b1));
}
__device__ __forceinline__ void splitf(float v, bf16& h, bf16& l) {
    h = __float2bfloat16(v); l = __float2bfloat16(v - __bfloat162float(h));
}
__device__ __forceinline__ uint32_t pk2(bf16 a, bf16 b) {
    return ((uint32_t)__bfloat16_as_ushort(b) << 16) | __bfloat16_as_ushort(a);
}
// fast split pair: hp = bf16x2(lo=v0, hi=v1); limbs bit-identical to splitf
__device__ __forceinline__ uint32_t pkbf2(float v0, float v1) {
    __nv_bfloat162 p = __float22bfloat162_rn(make_float2(v0, v1));
    return *reinterpret_cast<uint32_t*>(&p);
}
__device__ __forceinline__ float bflo(uint32_t p) { return __uint_as_float(p << 16); }
__device__ __forceinline__ float bfhi(uint32_t p) { return __uint_as_float(p & 0xffff0000u); }
__device__ __forceinline__ float ex2f(float x) {
    float y; asm("ex2.approx.f32 %0, %1;" : "=f"(y) : "f"(x)); return y;
}

// ---------------- scratch ----------------
__device__ bf16 g_xh[ROWS*DIM],     g_xl[ROWS*DIM];
__device__ bf16 g_wqlh[QLD*DIM],    g_wqll[QLD*DIM];
__device__ bf16 g_wkvh[KVLD*LATENT],g_wkvl[KVLD*LATENT];
__device__ bf16 g_woh[DIM*DIM],     g_wol[DIM*DIM];
__device__ float g_bql[QLD], g_bkv[KVLD];
__device__ bf16 g_qlh[(size_t)ROWS*QLD],  g_qll[(size_t)ROWS*QLD];
__device__ bf16 g_kvh[(size_t)ROWS*KVLD], g_kvl[(size_t)ROWS*KVLD];
__device__ bf16 g_vth[ROWS*DIM],    g_vtl[ROWS*DIM];
__device__ bf16 g_ah[ROWS*DIM],     g_al[ROWS*DIM];

// ---------------- smem tile loaders (cp.async, SW128), 256 threads ----------
__device__ __forceinline__ void cp_tile(uint32_t sdst, const bf16* src, int ld, int t) {
    #pragma unroll
    for (int i = 0; i < 4; i++) {
        int id = i*256 + t, r = id >> 3, c = id & 7;
        cpa16(sdst + SWZ(r*128 + c*16), src + (size_t)r*ld + c*8);
    }
}
__device__ __forceinline__ void cp_t64(uint32_t sdst, const bf16* src, int ld, int t) {
    #pragma unroll
    for (int i = 0; i < 2; i++) {
        int id = i*256 + t, r = id >> 3, c = id & 7;
        cpa16(sdst + SWZ(r*128 + c*16), src + (size_t)r*ld + c*8);
    }
}

// ---------------- fragment loaders ----------------
__device__ __forceinline__ void ldA(uint32_t sb, int m0, int ks, int lane, uint32_t* f) {
    int g = lane >> 3, r = lane & 7;
    int row = m0 + ((g & 1) << 3) + r, kc = ks*16 + ((g >> 1) << 3);
    ldsm4(sb + SWZ(row*128 + kc*2), f[0], f[1], f[2], f[3]);
}
__device__ __forceinline__ void ldB(uint32_t sb, int n0, int ks, int lane, uint32_t* f) {
    int g = lane >> 3, r = lane & 7;
    int row = n0 + ((g >> 1) << 3) + r, kc = ks*16 + ((g & 1) << 3);
    ldsm4(sb + SWZ(row*128 + kc*2), f[0], f[1], f[2], f[3]);
}

// ---------------- conversion kernels ----------------
__global__ void split_x(const float* __restrict__ x, bf16* __restrict__ oh, bf16* __restrict__ ol, int n) {
    for (int i = blockIdx.x*blockDim.x + threadIdx.x; i < n; i += gridDim.x*blockDim.x) {
        bf16 h, l; splitf(x[i], h, l); oh[i] = h; ol[i] = l;
    }
}
struct W5 {
    const float* W[5];
    bf16 *oh[5], *ol[5];
    int K[5], N[5], b0[6];
};
__global__ void wsplit_all(W5 j) {
    __shared__ float tile[32][33];
    int bid = blockIdx.x, ji = 0;
    #pragma unroll
    for (int z = 1; z < 5; z++) if (bid >= j.b0[z]) ji = z;
    int rel = bid - j.b0[ji];
    int K = j.K[ji], N = j.N[ji];
    int nbx = N >> 5;
    int bx = (rel % nbx) * 32, by = (rel / nbx) * 32;
    const float* W = j.W[ji];
    bf16 *oh = j.oh[ji], *ol = j.ol[ji];
    int tx = threadIdx.x & 31, ty = threadIdx.x >> 5;
    #pragma unroll
    for (int i = 0; i < 4; i++) tile[i*8+ty][tx] = W[(size_t)(by + i*8+ty)*N + bx + tx];
    __syncthreads();
    #pragma unroll
    for (int i = 0; i < 4; i++) {
        bf16 h, l; splitf(tile[tx][i*8+ty], h, l);
        size_t o = (size_t)(bx + i*8+ty)*K + by + tx;
        oh[o] = h; ol[o] = l;
    }
}
__global__ void biascat(const float* bq, const float* bl, const float* bk, const float* bv,
                        float* bql, float* bkv) {
    int t = blockIdx.x*blockDim.x + threadIdx.x;
    if (t < QLD)  bql[t] = (t < DIM) ? bq[t] : bl[t - DIM];
    if (t < KVLD) bkv[t] = (t < DIM) ? bk[t] : bv[t - DIM];
}
__global__ void vtsplit(const bf16* __restrict__ kvh, const bf16* __restrict__ kvl,
                        bf16* __restrict__ oh, bf16* __restrict__ ol) {
    __shared__ uint16_t th[32][33], tl[32][33];
    int s0 = blockIdx.x*32, d0 = blockIdx.y*32, b = blockIdx.z;
    int tx = threadIdx.x & 31, ty = threadIdx.x >> 5;
    #pragma unroll
    for (int i = 0; i < 4; i++) {
        size_t src = ((size_t)(b*SEQ + s0 + i*8+ty))*KVLD + DIM + d0 + tx;
        th[i*8+ty][tx] = __bfloat16_as_ushort(kvh[src]);
        tl[i*8+ty][tx] = __bfloat16_as_ushort(kvl[src]);
    }
    __syncthreads();
    #pragma unroll
    for (int i = 0; i < 4; i++) {
        size_t dst = ((size_t)(b*DIM + d0 + i*8+ty))*SEQ + s0 + tx;
        oh[dst] = __ushort_as_bfloat16(th[tx][i*8+ty]);
        ol[dst] = __ushort_as_bfloat16(tl[tx][i*8+ty]);
    }
}

// ---------------- GEMM: 128x64 CTA tile, 256 thr, 2 CTA/SM (R9 winner) ------
#define G_STAGE 49152
#define G_SMEM  (2*G_STAGE)

template<int OUTMODE>
__global__ __launch_bounds__(256, 2) void gemm_tc(
    const bf16* __restrict__ Ah, const bf16* __restrict__ Al,
    const bf16* __restrict__ Bh, const bf16* __restrict__ Bl,
    const float* __restrict__ bias,
    float* __restrict__ Cf, bf16* __restrict__ Ch, bf16* __restrict__ Cl,
    int N, int K, int lda, int ncut, float s0, float s1)
{
    extern __shared__ char smem[];
    const int t = threadIdx.x, lane = t & 31, w = t >> 5;
    const int wm = w >> 1, wn = w & 1;
    const int row0 = blockIdx.y*128, col0 = blockIdx.x*64;
    const uint32_t sbase = smem_u32(smem);

    float acc[2][4][4] = {};
    const int nit = K / 64;

    {
        cp_tile(sbase,          Ah + (size_t)row0*lda, lda, t);
        cp_tile(sbase + 16384,  Al + (size_t)row0*lda, lda, t);
        cp_t64(sbase + 32768,   Bh + (size_t)col0*K, K, t);
        cp_t64(sbase + 40960,   Bl + (size_t)col0*K, K, t);
        CPA_COMMIT();
    }

    for (int it = 0; it < nit; it++) {
        if (it + 1 < nit) {
            uint32_t sn = sbase + ((it + 1) & 1) * G_STAGE;
            int k0 = (it + 1) * 64;
            cp_tile(sn,         Ah + (size_t)row0*lda + k0, lda, t);
            cp_tile(sn + 16384, Al + (size_t)row0*lda + k0, lda, t);
            cp_t64(sn + 32768,  Bh + (size_t)col0*K + k0, K, t);
            cp_t64(sn + 40960,  Bl + (size_t)col0*K + k0, K, t);
            CPA_COMMIT();
            CPA_WAIT1();
        } else {
            CPA_WAIT0();
        }
        __syncthreads();

        const uint32_t sAh = sbase + (it & 1) * G_STAGE;
        const uint32_t sAl = sAh + 16384, sBh = sAh + 32768, sBl = sAh + 40960;
        #pragma unroll
        for (int ks = 0; ks < 4; ks++) {
            uint32_t ah[2][4], al[2][4], bh[2][4], bl[2][4];
            #pragma unroll
            for (int mt = 0; mt < 2; mt++) {
                ldA(sAh, wm*32 + mt*16, ks, lane, ah[mt]);
                ldA(sAl, wm*32 + mt*16, ks, lane, al[mt]);
            }
            #pragma unroll
            for (int pn = 0; pn < 2; pn++) {
                ldB(sBh, wn*32 + pn*16, ks, lane, bh[pn]);
                ldB(sBl, wn*32 + pn*16, ks, lane, bl[pn]);
            }
            #pragma unroll
            for (int mt = 0; mt < 2; mt++)
                #pragma unroll
                for (int nt = 0; nt < 4; nt++) {
                    int pn = nt >> 1, ix = (nt & 1)*2;
                    hmma(acc[mt][nt], ah[mt], bh[pn][ix], bh[pn][ix+1]);
                    hmma(acc[mt][nt], ah[mt], bl[pn][ix], bl[pn][ix+1]);
                    hmma(acc[mt][nt], al[mt], bh[pn][ix], bh[pn][ix+1]);
                }
        }
        __syncthreads();
    }

    const int g = lane >> 2, cl2 = (lane & 3)*2;
    #pragma unroll
    for (int mt = 0; mt < 2; mt++) {
        int r0 = row0 + wm*32 + mt*16 + g;
        #pragma unroll
        for (int nt = 0; nt < 4; nt++) {
            int c = col0 + wn*32 + nt*8 + cl2;
            float sc0 = (c < ncut) ? s0 : s1;
            float sc1 = (c + 1 < ncut) ? s0 : s1;
            float b0v = bias[c], b1v = bias[c+1];
            float v00 = (acc[mt][nt][0] + b0v)*sc0, v01 = (acc[mt][nt][1] + b1v)*sc1;
            float v10 = (acc[mt][nt][2] + b0v)*sc0, v11 = (acc[mt][nt][3] + b1v)*sc1;
            if (OUTMODE == 0) {
                *reinterpret_cast<float2*>(Cf + (size_t)r0*N + c)     = make_float2(v00, v01);
                *reinterpret_cast<float2*>(Cf + (size_t)(r0+8)*N + c) = make_float2(v10, v11);
            } else {
                uint32_t hp0 = pkbf2(v00, v01);
                uint32_t lp0 = pkbf2(v00 - bflo(hp0), v01 - bfhi(hp0));
                *reinterpret_cast<uint32_t*>(Ch + (size_t)r0*N + c) = hp0;
                *reinterpret_cast<uint32_t*>(Cl + (size_t)r0*N + c) = lp0;
                uint32_t hp1 = pkbf2(v10, v11);
                uint32_t lp1 = pkbf2(v10 - bflo(hp1), v11 - bfhi(hp1));
                *reinterpret_cast<uint32_t*>(Ch + (size_t)(r0+8)*N + c) = hp1;
                *reinterpret_cast<uint32_t*>(Cl + (size_t)(r0+8)*N + c) = lp1;
            }
        }
    }
}

// ---------------- flash attention (R9 structure; ex2 softmax, fast packing) -
// Q pre-scaled by QSCALE*log2e in the projection -> p = 2^(s - 6*log2e).
#define A_QBUF  32768
#define A_STAGE 32768
#define A_SMEM  (A_QBUF + 2*A_STAGE)

__global__ __launch_bounds__(256, 2) void attn_tc(
    const bf16* __restrict__ qh, const bf16* __restrict__ ql,
    const bf16* __restrict__ kh, const bf16* __restrict__ kl,
    const bf16* __restrict__ vth, const bf16* __restrict__ vtl,
    bf16* __restrict__ oh, bf16* __restrict__ ol)
{
    extern __shared__ char smem[];
    const int t = threadIdx.x, lane = t & 31, w = t >> 5;
    const int q0 = blockIdx.x*128, h = blockIdx.y, b = blockIdx.z;
    const uint32_t sbase = smem_u32(smem);
    const uint32_t sQh = sbase, sQl = sbase + 16384;
    const uint32_t sKV = sbase + A_QBUF;
    const size_t qbase = ((size_t)(b*SEQ + q0))*QLD + h*DHEAD;
    const size_t kbase = ((size_t)(b*SEQ))*KVLD + h*DHEAD;
    const size_t vbase = ((size_t)(b*DIM + h*DHEAD))*SEQ;

    cp_tile(sQh, qh + qbase, QLD, t);
    cp_tile(sQl, ql + qbase, QLD, t);
    CPA_COMMIT();
    cp_t64(sKV,         kh + kbase, KVLD, t);
    cp_t64(sKV + 8192,  kl + kbase, KVLD, t);
    cp_t64(sKV + 16384, vth + vbase, SEQ, t);
    cp_t64(sKV + 24576, vtl + vbase, SEQ, t);
    CPA_COMMIT();
    CPA_WAIT1();
    __syncthreads();

    uint32_t qf[4][4], qg[4][4];
    #pragma unroll
    for (int ks = 0; ks < 4; ks++) {
        ldA(sQh, w*16, ks, lane, qf[ks]);
        ldA(sQl, w*16, ks, lane, qg[ks]);
    }

    float o[8][4] = {};
    float lsum0 = 0.f, lsum1 = 0.f;
    const int nkb = SEQ / 64;

    for (int kb = 0; kb < nkb; kb++) {
        if (kb + 1 < nkb) {
            uint32_t sn = sKV + ((kb + 1) & 1) * A_STAGE;
            cp_t64(sn,         kh + kbase + (size_t)(kb+1)*64*KVLD, KVLD, t);
            cp_t64(sn + 8192,  kl + kbase + (size_t)(kb+1)*64*KVLD, KVLD, t);
            cp_t64(sn + 16384, vth + vbase + (kb+1)*64, SEQ, t);
            cp_t64(sn + 24576, vtl + vbase + (kb+1)*64, SEQ, t);
            CPA_COMMIT();
            CPA_WAIT1();
        } else {
            CPA_WAIT0();
        }
        __syncthreads();

        const uint32_t st = sKV + (kb & 1) * A_STAGE;
        const uint32_t sKh = st, sKl = st + 8192, sVh = st + 16384, sVl = st + 24576;

        // ---- S = Q K^T : full 3-pass ----
        float s[8][4] = {};
        #pragma unroll
        for (int ks = 0; ks < 4; ks++) {
            #pragma unroll
            for (int pn = 0; pn < 4; pn++) {
                uint32_t bh4[4], bl4[4];
                ldB(sKh, pn*16, ks, lane, bh4);
                ldB(sKl, pn*16, ks, lane, bl4);
                #pragma unroll
                for (int hf = 0; hf < 2; hf++) {
                    int nt = pn*2 + hf, ix = hf*2;
                    hmma(s[nt], qf[ks], bh4[ix], bh4[ix+1]);
                    hmma(s[nt], qf[ks], bl4[ix], bl4[ix+1]);
                    hmma(s[nt], qg[ks], bh4[ix], bh4[ix+1]);
                }
            }
        }

        // ---- softmax (ex2) + fast hi/lo pack ----
        uint32_t ph[4][4], pl[4][4];
        #pragma unroll
        for (int nt = 0; nt < 8; nt++) {
            float e0 = ex2f(s[nt][0] - EXP_OFF2), e1 = ex2f(s[nt][1] - EXP_OFF2);
            float e2 = ex2f(s[nt][2] - EXP_OFF2), e3 = ex2f(s[nt][3] - EXP_OFF2);
            lsum0 += e0 + e1; lsum1 += e2 + e3;
            int kf = nt >> 1, ix = (nt & 1)*2;
            uint32_t hp0 = pkbf2(e0, e1);
            ph[kf][ix]   = hp0;
            pl[kf][ix]   = pkbf2(e0 - bflo(hp0), e1 - bfhi(hp0));
            uint32_t hp1 = pkbf2(e2, e3);
            ph[kf][ix+1] = hp1;
            pl[kf][ix+1] = pkbf2(e2 - bflo(hp1), e3 - bfhi(hp1));
        }

        // ---- O += P V : full 3-pass ----
        #pragma unroll
        for (int ks = 0; ks < 4; ks++) {
            #pragma unroll
            for (int dp = 0; dp < 4; dp++) {
                uint32_t vh4[4], vl4[4];
                ldB(sVh, dp*16, ks, lane, vh4);
                ldB(sVl, dp*16, ks, lane, vl4);
                #pragma unroll
                for (int hf = 0; hf < 2; hf++) {
                    int dt = dp*2 + hf, ix = hf*2;
                    hmma(o[dt], ph[ks], vh4[ix], vh4[ix+1]);
                    hmma(o[dt], ph[ks], vl4[ix], vl4[ix+1]);
                    hmma(o[dt], pl[ks], vh4[ix], vh4[ix+1]);
                }
            }
        }
        __syncthreads();
    }

    lsum0 += __shfl_xor_sync(0xffffffffu, lsum0, 1);
    lsum0 += __shfl_xor_sync(0xffffffffu, lsum0, 2);
    lsum1 += __shfl_xor_sync(0xffffffffu, lsum1, 1);
    lsum1 += __shfl_xor_sync(0xffffffffu, lsum1, 2);
    float inv0 = 1.0f / lsum0, inv1 = 1.0f / lsum1;

    const int g = lane >> 2, cl2 = (lane & 3)*2;
    const size_t r0 = (size_t)(b*SEQ + q0 + w*16 + g);
    #pragma unroll
    for (int dt = 0; dt < 8; dt++) {
        int c = h*DHEAD + dt*8 + cl2;
        float v0 = o[dt][0]*inv0, v1 = o[dt][1]*inv0;
        uint32_t hp0 = pkbf2(v0, v1);
        *reinterpret_cast<uint32_t*>(oh + r0*DIM + c) = hp0;
        *reinterpret_cast<uint32_t*>(ol + r0*DIM + c) = pkbf2(v0 - bflo(hp0), v1 - bfhi(hp0));
        float v2 = o[dt][2]*inv1, v3 = o[dt][3]*inv1;
        uint32_t hp1 = pkbf2(v2, v3);
        *reinterpret_cast<uint32_t*>(oh + (r0+8)*DIM + c) = hp1;
        *reinterpret_cast<uint32_t*>(ol + (r0+8)*DIM + c) = pkbf2(v2 - bflo(hp1), v3 - bfhi(hp1));
    }
}

// ---------------- launch ----------------
extern "C" void kernel_launch(void* const* d_in, const int* in_sizes, int n_in,
                              void* d_out, int out_size)
{
    (void)in_sizes; (void)n_in; (void)out_size;
    const float* x  = (const float*)d_in[0];
    const float* Wq = (const float*)d_in[1];  const float* bq = (const float*)d_in[2];
    const float* Wl = (const float*)d_in[3];  const float* bl = (const float*)d_in[4];
    const float* Wk = (const float*)d_in[5];  const float* bk = (const float*)d_in[6];
    const float* Wv = (const float*)d_in[7];  const float* bv = (const float*)d_in[8];
    const float* Wo = (const float*)d_in[9];  const float* bo = (const float*)d_in[10];
    float* out = (float*)d_out;

    bf16 *xh,*xl,*wqlh,*wqll,*wkvh,*wkvl,*woh,*wol;
    bf16 *qlh,*qll,*kvh,*kvl,*vth,*vtl,*ah,*al;
    float *bqlp,*bkvp;
    cudaGetSymbolAddress((void**)&xh, g_xh);     cudaGetSymbolAddress((void**)&xl, g_xl);
    cudaGetSymbolAddress((void**)&wqlh, g_wqlh); cudaGetSymbolAddress((void**)&wqll, g_wqll);
    cudaGetSymbolAddress((void**)&wkvh, g_wkvh); cudaGetSymbolAddress((void**)&wkvl, g_wkvl);
    cudaGetSymbolAddress((void**)&woh, g_woh);   cudaGetSymbolAddress((void**)&wol, g_wol);
    cudaGetSymbolAddress((void**)&qlh, g_qlh);   cudaGetSymbolAddress((void**)&qll, g_qll);
    cudaGetSymbolAddress((void**)&kvh, g_kvh);   cudaGetSymbolAddress((void**)&kvl, g_kvl);
    cudaGetSymbolAddress((void**)&vth, g_vth);   cudaGetSymbolAddress((void**)&vtl, g_vtl);
    cudaGetSymbolAddress((void**)&ah, g_ah);     cudaGetSymbolAddress((void**)&al, g_al);
    cudaGetSymbolAddress((void**)&bqlp, g_bql);  cudaGetSymbolAddress((void**)&bkvp, g_bkv);

    cudaFuncSetAttribute(gemm_tc<0>, cudaFuncAttributeMaxDynamicSharedMemorySize, G_SMEM);
    cudaFuncSetAttribute(gemm_tc<1>, cudaFuncAttributeMaxDynamicSharedMemorySize, G_SMEM);
    cudaFuncSetAttribute(attn_tc,    cudaFuncAttributeMaxDynamicSharedMemorySize, A_SMEM);

    split_x<<<2048, 256>>>(x, xh, xl, ROWS*DIM);

    W5 j;
    j.W[0]=Wq; j.oh[0]=wqlh;                       j.ol[0]=wqll;                       j.K[0]=DIM;    j.N[0]=DIM;
    j.W[1]=Wl; j.oh[1]=wqlh + (size_t)DIM*DIM;     j.ol[1]=wqll + (size_t)DIM*DIM;     j.K[1]=DIM;    j.N[1]=LATENT;
    j.W[2]=Wk; j.oh[2]=wkvh;                       j.ol[2]=wkvl;                       j.K[2]=LATENT; j.N[2]=DIM;
    j.W[3]=Wv; j.oh[3]=wkvh + (size_t)DIM*LATENT;  j.ol[3]=wkvl + (size_t)DIM*LATENT;  j.K[3]=LATENT; j.N[3]=DIM;
    j.W[4]=Wo; j.oh[4]=woh;                        j.ol[4]=wol;                        j.K[4]=DIM;    j.N[4]=DIM;
    int nb = 0;
    for (int z = 0; z < 5; z++) { j.b0[z] = nb; nb += (j.N[z]/32)*(j.K[z]/32); }
    j.b0[5] = nb;
    wsplit_all<<<nb, 256>>>(j);
    biascat<<<8, 256>>>(bq, bl, bk, bv, bqlp, bkvp);

    // q scaled by QSCALE*log2e so softmax uses raw ex2
    gemm_tc<1><<<dim3(QLD/64, ROWS/128), 256, G_SMEM>>>(
        xh, xl, wqlh, wqll, bqlp, nullptr, qlh, qll, QLD, DIM, DIM, DIM, QSCALE*LOG2E, 1.0f);
    gemm_tc<1><<<dim3(KVLD/64, ROWS/128), 256, G_SMEM>>>(
        qlh + DIM, qll + DIM, wkvh, wkvl, bkvp, nullptr, kvh, kvl, KVLD, LATENT, QLD, 0, 1.0f, 1.0f);
    vtsplit<<<dim3(SEQ/32, DIM/32, BATCH), 256>>>(kvh, kvl, vth, vtl);
    attn_tc<<<dim3(SEQ/128, HEADS, BATCH), 256, A_SMEM>>>(qlh, qll, kvh, kvl, vth, vtl, ah, al);
    gemm_tc<0><<<dim3(DIM/64, ROWS/128), 256, G_SMEM>>>(
        ah, al, woh, wol, bo, out, nullptr, nullptr, DIM, DIM, DIM, 0, 1.0f, 1.0f);
}

// round 15
// speedup vs baseline: 1.5379x; 1.5379x over previous
#include <cuda_runtime.h>
#include <cuda_bf16.h>
#include <cstdint>

#define BATCH 2
#define SEQ   2048
#define DIM   1024
#define HEADS 16
#define DHEAD 64
#define LATENT 256
#define ROWS  (BATCH*SEQ)
#define QSCALE 0.125f
#define LOG2E  1.44269504088896f
#define EXP_OFF2 8.65617024533378f   /* 6.0 * log2(e) */
#define QLD  1280
#define KVLD 2048

typedef __nv_bfloat16 bf16;

#define SWZ(x) ((uint32_t)(x) ^ ((((uint32_t)(x)) >> 3) & 0x70))

__device__ __forceinline__ uint32_t smem_u32(const void* p) {
    uint32_t a;
    asm("{ .reg .u64 t; cvta.to.shared.u64 t, %1; cvt.u32.u64 %0, t; }" : "=r"(a) : "l"(p));
    return a;
}
__device__ __forceinline__ void cpa16(uint32_t d, const void* s) {
    asm volatile("cp.async.cg.shared.global [%0], [%1], 16;" :: "r"(d), "l"(s));
}
#define CPA_COMMIT() asm volatile("cp.async.commit_group;" ::: "memory")
#define CPA_WAIT0()  asm volatile("cp.async.wait_group 0;" ::: "memory")
#define CPA_WAIT1()  asm volatile("cp.async.wait_group 1;" ::: "memory")

__device__ __forceinline__ void ldsm4(uint32_t a, uint32_t& r0, uint32_t& r1, uint32_t& r2, uint32_t& r3) {
    asm volatile("ldmatrix.sync.aligned.m8n8.x4.shared.b16 {%0,%1,%2,%3}, [%4];"
                 : "=r"(r0), "=r"(r1), "=r"(r2), "=r"(r3) : "r"(a));
}
__device__ __forceinline__ void hmma(float* c, const uint32_t* a, uint32_t b0, uint32_t b1) {
    asm volatile("mma.sync.aligned.m16n8k16.row.col.f32.bf16.bf16.f32 "
        "{%0,%1,%2,%3}, {%4,%5,%6,%7}, {%8,%9}, {%0,%1,%2,%3};"
        : "+f"(c[0]), "+f"(c[1]), "+f"(c[2]), "+f"(c[3])
        : "r"(a[0]), "r"(a[1]), "r"(a[2]), "r"(a[3]), "r"(b0), "r"(b1));
}
__device__ __forceinline__ void splitf(float v, bf16& h, bf16& l) {
    h = __float2bfloat16(v); l = __float2bfloat16(v - __bfloat162float(h));
}
__device__ __forceinline__ uint32_t pk2(bf16 a, bf16 b) {
    return ((uint32_t)__bfloat16_as_ushort(b) << 16) | __bfloat16_as_ushort(a);
}
// fast split pair: hp = bf16x2(lo=v0, hi=v1); limbs bit-identical to splitf
__device__ __forceinline__ uint32_t pkbf2(float v0, float v1) {
    __nv_bfloat162 p = __float22bfloat162_rn(make_float2(v0, v1));
    return *reinterpret_cast<uint32_t*>(&p);
}
__device__ __forceinline__ float bflo(uint32_t p) { return __uint_as_float(p << 16); }
__device__ __forceinline__ float bfhi(uint32_t p) { return __uint_as_float(p & 0xffff0000u); }
__device__ __forceinline__ float ex2f(float x) {
    float y; asm("ex2.approx.f32 %0, %1;" : "=f"(y) : "f"(x)); return y;
}

// ---------------- scratch ----------------
__device__ bf16 g_xh[ROWS*DIM],     g_xl[ROWS*DIM];
__device__ bf16 g_wqlh[QLD*DIM],    g_wqll[QLD*DIM];
__device__ bf16 g_wkvh[KVLD*LATENT],g_wkvl[KVLD*LATENT];
__device__ bf16 g_woh[DIM*DIM],     g_wol[DIM*DIM];
__device__ float g_bql[QLD], g_bkv[KVLD];
__device__ bf16 g_qlh[(size_t)ROWS*QLD],  g_qll[(size_t)ROWS*QLD];
__device__ bf16 g_kvh[(size_t)ROWS*KVLD], g_kvl[(size_t)ROWS*KVLD];
__device__ bf16 g_vth[ROWS*DIM],    g_vtl[ROWS*DIM];
__device__ bf16 g_ah[ROWS*DIM],     g_al[ROWS*DIM];

// ---------------- smem tile loaders (cp.async, SW128), 256 threads ----------
__device__ __forceinline__ void cp_tile(uint32_t sdst, const bf16* src, int ld, int t) {
    #pragma unroll
    for (int i = 0; i < 4; i++) {
        int id = i*256 + t, r = id >> 3, c = id & 7;
        cpa16(sdst + SWZ(r*128 + c*16), src + (size_t)r*ld + c*8);
    }
}
__device__ __forceinline__ void cp_t64(uint32_t sdst, const bf16* src, int ld, int t) {
    #pragma unroll
    for (int i = 0; i < 2; i++) {
        int id = i*256 + t, r = id >> 3, c = id & 7;
        cpa16(sdst + SWZ(r*128 + c*16), src + (size_t)r*ld + c*8);
    }
}

// ---------------- fragment loaders ----------------
__device__ __forceinline__ void ldA(uint32_t sb, int m0, int ks, int lane, uint32_t* f) {
    int g = lane >> 3, r = lane & 7;
    int row = m0 + ((g & 1) << 3) + r, kc = ks*16 + ((g >> 1) << 3);
    ldsm4(sb + SWZ(row*128 + kc*2), f[0], f[1], f[2], f[3]);
}
__device__ __forceinline__ void ldB(uint32_t sb, int n0, int ks, int lane, uint32_t* f) {
    int g = lane >> 3, r = lane & 7;
    int row = n0 + ((g >> 1) << 3) + r, kc = ks*16 + ((g & 1) << 3);
    ldsm4(sb + SWZ(row*128 + kc*2), f[0], f[1], f[2], f[3]);
}

// ---------------- conversion kernels ----------------
__global__ void split_x(const float* __restrict__ x, bf16* __restrict__ oh, bf16* __restrict__ ol, int n) {
    for (int i = blockIdx.x*blockDim.x + threadIdx.x; i < n; i += gridDim.x*blockDim.x) {
        bf16 h, l; splitf(x[i], h, l); oh[i] = h; ol[i] = l;
    }
}
struct W5 {
    const float* W[5];
    bf16 *oh[5], *ol[5];
    int K[5], N[5], b0[6];
};
__global__ void wsplit_all(W5 j) {
    __shared__ float tile[32][33];
    int bid = blockIdx.x, ji = 0;
    #pragma unroll
    for (int z = 1; z < 5; z++) if (bid >= j.b0[z]) ji = z;
    int rel = bid - j.b0[ji];
    int K = j.K[ji], N = j.N[ji];
    int nbx = N >> 5;
    int bx = (rel % nbx) * 32, by = (rel / nbx) * 32;
    const float* W = j.W[ji];
    bf16 *oh = j.oh[ji], *ol = j.ol[ji];
    int tx = threadIdx.x & 31, ty = threadIdx.x >> 5;
    #pragma unroll
    for (int i = 0; i < 4; i++) tile[i*8+ty][tx] = W[(size_t)(by + i*8+ty)*N + bx + tx];
    __syncthreads();
    #pragma unroll
    for (int i = 0; i < 4; i++) {
        bf16 h, l; splitf(tile[tx][i*8+ty], h, l);
        size_t o = (size_t)(bx + i*8+ty)*K + by + tx;
        oh[o] = h; ol[o] = l;
    }
}
__global__ void biascat(const float* bq, const float* bl, const float* bk, const float* bv,
                        float* bql, float* bkv) {
    int t = blockIdx.x*blockDim.x + threadIdx.x;
    if (t < QLD)  bql[t] = (t < DIM) ? bq[t] : bl[t - DIM];
    if (t < KVLD) bkv[t] = (t < DIM) ? bk[t] : bv[t - DIM];
}
__global__ void vtsplit(const bf16* __restrict__ kvh, const bf16* __restrict__ kvl,
                        bf16* __restrict__ oh, bf16* __restrict__ ol) {
    __shared__ uint16_t th[32][33], tl[32][33];
    int s0 = blockIdx.x*32, d0 = blockIdx.y*32, b = blockIdx.z;
    int tx = threadIdx.x & 31, ty = threadIdx.x >> 5;
    #pragma unroll
    for (int i = 0; i < 4; i++) {
        size_t src = ((size_t)(b*SEQ + s0 + i*8+ty))*KVLD + DIM + d0 + tx;
        th[i*8+ty][tx] = __bfloat16_as_ushort(kvh[src]);
        tl[i*8+ty][tx] = __bfloat16_as_ushort(kvl[src]);
    }
    __syncthreads();
    #pragma unroll
    for (int i = 0; i < 4; i++) {
        size_t dst = ((size_t)(b*DIM + d0 + i*8+ty))*SEQ + s0 + tx;
        oh[dst] = __ushort_as_bfloat16(th[tx][i*8+ty]);
        ol[dst] = __ushort_as_bfloat16(tl[tx][i*8+ty]);
    }
}

// ---------------- GEMM: 128x64 CTA tile, 256 thr, 2 CTA/SM (R9 winner) ------
#define G_STAGE 49152
#define G_SMEM  (2*G_STAGE)

template<int OUTMODE>
__global__ __launch_bounds__(256, 2) void gemm_tc(
    const bf16* __restrict__ Ah, const bf16* __restrict__ Al,
    const bf16* __restrict__ Bh, const bf16* __restrict__ Bl,
    const float* __restrict__ bias,
    float* __restrict__ Cf, bf16* __restrict__ Ch, bf16* __restrict__ Cl,
    int N, int K, int lda, int ncut, float s0, float s1)
{
    extern __shared__ char smem[];
    const int t = threadIdx.x, lane = t & 31, w = t >> 5;
    const int wm = w >> 1, wn = w & 1;
    const int row0 = blockIdx.y*128, col0 = blockIdx.x*64;
    const uint32_t sbase = smem_u32(smem);

    float acc[2][4][4] = {};
    const int nit = K / 64;

    {
        cp_tile(sbase,          Ah + (size_t)row0*lda, lda, t);
        cp_tile(sbase + 16384,  Al + (size_t)row0*lda, lda, t);
        cp_t64(sbase + 32768,   Bh + (size_t)col0*K, K, t);
        cp_t64(sbase + 40960,   Bl + (size_t)col0*K, K, t);
        CPA_COMMIT();
    }

    for (int it = 0; it < nit; it++) {
        if (it + 1 < nit) {
            uint32_t sn = sbase + ((it + 1) & 1) * G_STAGE;
            int k0 = (it + 1) * 64;
            cp_tile(sn,         Ah + (size_t)row0*lda + k0, lda, t);
            cp_tile(sn + 16384, Al + (size_t)row0*lda + k0, lda, t);
            cp_t64(sn + 32768,  Bh + (size_t)col0*K + k0, K, t);
            cp_t64(sn + 40960,  Bl + (size_t)col0*K + k0, K, t);
            CPA_COMMIT();
            CPA_WAIT1();
        } else {
            CPA_WAIT0();
        }
        __syncthreads();

        const uint32_t sAh = sbase + (it & 1) * G_STAGE;
        const uint32_t sAl = sAh + 16384, sBh = sAh + 32768, sBl = sAh + 40960;
        #pragma unroll
        for (int ks = 0; ks < 4; ks++) {
            uint32_t ah[2][4], al[2][4], bh[2][4], bl[2][4];
            #pragma unroll
            for (int mt = 0; mt < 2; mt++) {
                ldA(sAh, wm*32 + mt*16, ks, lane, ah[mt]);
                ldA(sAl, wm*32 + mt*16, ks, lane, al[mt]);
            }
            #pragma unroll
            for (int pn = 0; pn < 2; pn++) {
                ldB(sBh, wn*32 + pn*16, ks, lane, bh[pn]);
                ldB(sBl, wn*32 + pn*16, ks, lane, bl[pn]);
            }
            #pragma unroll
            for (int mt = 0; mt < 2; mt++)
                #pragma unroll
                for (int nt = 0; nt < 4; nt++) {
                    int pn = nt >> 1, ix = (nt & 1)*2;
                    hmma(acc[mt][nt], ah[mt], bh[pn][ix], bh[pn][ix+1]);
                    hmma(acc[mt][nt], ah[mt], bl[pn][ix], bl[pn][ix+1]);
                    hmma(acc[mt][nt], al[mt], bh[pn][ix], bh[pn][ix+1]);
                }
        }
        __syncthreads();
    }

    const int g = lane >> 2, cl2 = (lane & 3)*2;
    #pragma unroll
    for (int mt = 0; mt < 2; mt++) {
        int r0 = row0 + wm*32 + mt*16 + g;
        #pragma unroll
        for (int nt = 0; nt < 4; nt++) {
            int c = col0 + wn*32 + nt*8 + cl2;
            float sc0 = (c < ncut) ? s0 : s1;
            float sc1 = (c + 1 < ncut) ? s0 : s1;
            float b0v = bias[c], b1v = bias[c+1];
            float v00 = (acc[mt][nt][0] + b0v)*sc0, v01 = (acc[mt][nt][1] + b1v)*sc1;
            float v10 = (acc[mt][nt][2] + b0v)*sc0, v11 = (acc[mt][nt][3] + b1v)*sc1;
            if (OUTMODE == 0) {
                *reinterpret_cast<float2*>(Cf + (size_t)r0*N + c)     = make_float2(v00, v01);
                *reinterpret_cast<float2*>(Cf + (size_t)(r0+8)*N + c) = make_float2(v10, v11);
            } else {
                uint32_t hp0 = pkbf2(v00, v01);
                uint32_t lp0 = pkbf2(v00 - bflo(hp0), v01 - bfhi(hp0));
                *reinterpret_cast<uint32_t*>(Ch + (size_t)r0*N + c) = hp0;
                *reinterpret_cast<uint32_t*>(Cl + (size_t)r0*N + c) = lp0;
                uint32_t hp1 = pkbf2(v10, v11);
                uint32_t lp1 = pkbf2(v10 - bflo(hp1), v11 - bfhi(hp1));
                *reinterpret_cast<uint32_t*>(Ch + (size_t)(r0+8)*N + c) = hp1;
                *reinterpret_cast<uint32_t*>(Cl + (size_t)(r0+8)*N + c) = lp1;
            }
        }
    }
}

// ---------------- flash attention (R9 structure; ex2 softmax, fast packing) -
// Q pre-scaled by QSCALE*log2e in the projection -> p = 2^(s - 6*log2e).
#define A_QBUF  32768
#define A_STAGE 32768
#define A_SMEM  (A_QBUF + 2*A_STAGE)

__global__ __launch_bounds__(256, 2) void attn_tc(
    const bf16* __restrict__ qh, const bf16* __restrict__ ql,
    const bf16* __restrict__ kh, const bf16* __restrict__ kl,
    const bf16* __restrict__ vth, const bf16* __restrict__ vtl,
    bf16* __restrict__ oh, bf16* __restrict__ ol)
{
    extern __shared__ char smem[];
    const int t = threadIdx.x, lane = t & 31, w = t >> 5;
    const int q0 = blockIdx.x*128, h = blockIdx.y, b = blockIdx.z;
    const uint32_t sbase = smem_u32(smem);
    const uint32_t sQh = sbase, sQl = sbase + 16384;
    const uint32_t sKV = sbase + A_QBUF;
    const size_t qbase = ((size_t)(b*SEQ + q0))*QLD + h*DHEAD;
    const size_t kbase = ((size_t)(b*SEQ))*KVLD + h*DHEAD;
    const size_t vbase = ((size_t)(b*DIM + h*DHEAD))*SEQ;

    cp_tile(sQh, qh + qbase, QLD, t);
    cp_tile(sQl, ql + qbase, QLD, t);
    CPA_COMMIT();
    cp_t64(sKV,         kh + kbase, KVLD, t);
    cp_t64(sKV + 8192,  kl + kbase, KVLD, t);
    cp_t64(sKV + 16384, vth + vbase, SEQ, t);
    cp_t64(sKV + 24576, vtl + vbase, SEQ, t);
    CPA_COMMIT();
    CPA_WAIT1();
    __syncthreads();

    uint32_t qf[4][4], qg[4][4];
    #pragma unroll
    for (int ks = 0; ks < 4; ks++) {
        ldA(sQh, w*16, ks, lane, qf[ks]);
        ldA(sQl, w*16, ks, lane, qg[ks]);
    }

    float o[8][4] = {};
    float lsum0 = 0.f, lsum1 = 0.f;
    const int nkb = SEQ / 64;

    for (int kb = 0; kb < nkb; kb++) {
        if (kb + 1 < nkb) {
            uint32_t sn = sKV + ((kb + 1) & 1) * A_STAGE;
            cp_t64(sn,         kh + kbase + (size_t)(kb+1)*64*KVLD, KVLD, t);
            cp_t64(sn + 8192,  kl + kbase + (size_t)(kb+1)*64*KVLD, KVLD, t);
            cp_t64(sn + 16384, vth + vbase + (kb+1)*64, SEQ, t);
            cp_t64(sn + 24576, vtl + vbase + (kb+1)*64, SEQ, t);
            CPA_COMMIT();
            CPA_WAIT1();
        } else {
            CPA_WAIT0();
        }
        __syncthreads();

        const uint32_t st = sKV + (kb & 1) * A_STAGE;
        const uint32_t sKh = st, sKl = st + 8192, sVh = st + 16384, sVl = st + 24576;

        // ---- S = Q K^T : full 3-pass ----
        float s[8][4] = {};
        #pragma unroll
        for (int ks = 0; ks < 4; ks++) {
            #pragma unroll
            for (int pn = 0; pn < 4; pn++) {
                uint32_t bh4[4], bl4[4];
                ldB(sKh, pn*16, ks, lane, bh4);
                ldB(sKl, pn*16, ks, lane, bl4);
                #pragma unroll
                for (int hf = 0; hf < 2; hf++) {
                    int nt = pn*2 + hf, ix = hf*2;
                    hmma(s[nt], qf[ks], bh4[ix], bh4[ix+1]);
                    hmma(s[nt], qf[ks], bl4[ix], bl4[ix+1]);
                    hmma(s[nt], qg[ks], bh4[ix], bh4[ix+1]);
                }
            }
        }

        // ---- softmax (ex2) + fast hi/lo pack ----
        uint32_t ph[4][4], pl[4][4];
        #pragma unroll
        for (int nt = 0; nt < 8; nt++) {
            float e0 = ex2f(s[nt][0] - EXP_OFF2), e1 = ex2f(s[nt][1] - EXP_OFF2);
            float e2 = ex2f(s[nt][2] - EXP_OFF2), e3 = ex2f(s[nt][3] - EXP_OFF2);
            lsum0 += e0 + e1; lsum1 += e2 + e3;
            int kf = nt >> 1, ix = (nt & 1)*2;
            uint32_t hp0 = pkbf2(e0, e1);
            ph[kf][ix]   = hp0;
            pl[kf][ix]   = pkbf2(e0 - bflo(hp0), e1 - bfhi(hp0));
            uint32_t hp1 = pkbf2(e2, e3);
            ph[kf][ix+1] = hp1;
            pl[kf][ix+1] = pkbf2(e2 - bflo(hp1), e3 - bfhi(hp1));
        }

        // ---- O += P V : full 3-pass ----
        #pragma unroll
        for (int ks = 0; ks < 4; ks++) {
            #pragma unroll
            for (int dp = 0; dp < 4; dp++) {
                uint32_t vh4[4], vl4[4];
                ldB(sVh, dp*16, ks, lane, vh4);
                ldB(sVl, dp*16, ks, lane, vl4);
                #pragma unroll
                for (int hf = 0; hf < 2; hf++) {
                    int dt = dp*2 + hf, ix = hf*2;
                    hmma(o[dt], ph[ks], vh4[ix], vh4[ix+1]);
                    hmma(o[dt], ph[ks], vl4[ix], vl4[ix+1]);
                    hmma(o[dt], pl[ks], vh4[ix], vh4[ix+1]);
                }
            }
        }
        __syncthreads();
    }

    lsum0 += __shfl_xor_sync(0xffffffffu, lsum0, 1);
    lsum0 += __shfl_xor_sync(0xffffffffu, lsum0, 2);
    lsum1 += __shfl_xor_sync(0xffffffffu, lsum1, 1);
    lsum1 += __shfl_xor_sync(0xffffffffu, lsum1, 2);
    float inv0 = 1.0f / lsum0, inv1 = 1.0f / lsum1;

    const int g = lane >> 2, cl2 = (lane & 3)*2;
    const size_t r0 = (size_t)(b*SEQ + q0 + w*16 + g);
    #pragma unroll
    for (int dt = 0; dt < 8; dt++) {
        int c = h*DHEAD + dt*8 + cl2;
        float v0 = o[dt][0]*inv0, v1 = o[dt][1]*inv0;
        uint32_t hp0 = pkbf2(v0, v1);
        *reinterpret_cast<uint32_t*>(oh + r0*DIM + c) = hp0;
        *reinterpret_cast<uint32_t*>(ol + r0*DIM + c) = pkbf2(v0 - bflo(hp0), v1 - bfhi(hp0));
        float v2 = o[dt][2]*inv1, v3 = o[dt][3]*inv1;
        uint32_t hp1 = pkbf2(v2, v3);
        *reinterpret_cast<uint32_t*>(oh + (r0+8)*DIM + c) = hp1;
        *reinterpret_cast<uint32_t*>(ol + (r0+8)*DIM + c) = pkbf2(v2 - bflo(hp1), v3 - bfhi(hp1));
    }
}

// ---------------- launch ----------------
extern "C" void kernel_launch(void* const* d_in, const int* in_sizes, int n_in,
                              void* d_out, int out_size)
{
    (void)in_sizes; (void)n_in; (void)out_size;
    const float* x  = (const float*)d_in[0];
    const float* Wq = (const float*)d_in[1];  const float* bq = (const float*)d_in[2];
    const float* Wl = (const float*)d_in[3];  const float* bl = (const float*)d_in[4];
    const float* Wk = (const float*)d_in[5];  const float* bk = (const float*)d_in[6];
    const float* Wv = (const float*)d_in[7];  const float* bv = (const float*)d_in[8];
    const float* Wo = (const float*)d_in[9];  const float* bo = (const float*)d_in[10];
    float* out = (float*)d_out;

    bf16 *xh,*xl,*wqlh,*wqll,*wkvh,*wkvl,*woh,*wol;
    bf16 *qlh,*qll,*kvh,*kvl,*vth,*vtl,*ah,*al;
    float *bqlp,*bkvp;
    cudaGetSymbolAddress((void**)&xh, g_xh);     cudaGetSymbolAddress((void**)&xl, g_xl);
    cudaGetSymbolAddress((void**)&wqlh, g_wqlh); cudaGetSymbolAddress((void**)&wqll, g_wqll);
    cudaGetSymbolAddress((void**)&wkvh, g_wkvh); cudaGetSymbolAddress((void**)&wkvl, g_wkvl);
    cudaGetSymbolAddress((void**)&woh, g_woh);   cudaGetSymbolAddress((void**)&wol, g_wol);
    cudaGetSymbolAddress((void**)&qlh, g_qlh);   cudaGetSymbolAddress((void**)&qll, g_qll);
    cudaGetSymbolAddress((void**)&kvh, g_kvh);   cudaGetSymbolAddress((void**)&kvl, g_kvl);
    cudaGetSymbolAddress((void**)&vth, g_vth);   cudaGetSymbolAddress((void**)&vtl, g_vtl);
    cudaGetSymbolAddress((void**)&ah, g_ah);     cudaGetSymbolAddress((void**)&al, g_al);
    cudaGetSymbolAddress((void**)&bqlp, g_bql);  cudaGetSymbolAddress((void**)&bkvp, g_bkv);

    cudaFuncSetAttribute(gemm_tc<0>, cudaFuncAttributeMaxDynamicSharedMemorySize, G_SMEM);
    cudaFuncSetAttribute(gemm_tc<1>, cudaFuncAttributeMaxDynamicSharedMemorySize, G_SMEM);
    cudaFuncSetAttribute(attn_tc,    cudaFuncAttributeMaxDynamicSharedMemorySize, A_SMEM);

    split_x<<<2048, 256>>>(x, xh, xl, ROWS*DIM);

    W5 j;
    j.W[0]=Wq; j.oh[0]=wqlh;                       j.ol[0]=wqll;                       j.K[0]=DIM;    j.N[0]=DIM;
    j.W[1]=Wl; j.oh[1]=wqlh + (size_t)DIM*DIM;     j.ol[1]=wqll + (size_t)DIM*DIM;     j.K[1]=DIM;    j.N[1]=LATENT;
    j.W[2]=Wk; j.oh[2]=wkvh;                       j.ol[2]=wkvl;                       j.K[2]=LATENT; j.N[2]=DIM;
    j.W[3]=Wv; j.oh[3]=wkvh + (size_t)DIM*LATENT;  j.ol[3]=wkvl + (size_t)DIM*LATENT;  j.K[3]=LATENT; j.N[3]=DIM;
    j.W[4]=Wo; j.oh[4]=woh;                        j.ol[4]=wol;                        j.K[4]=DIM;    j.N[4]=DIM;
    int nb = 0;
    for (int z = 0; z < 5; z++) { j.b0[z] = nb; nb += (j.N[z]/32)*(j.K[z]/32); }
    j.b0[5] = nb;
    wsplit_all<<<nb, 256>>>(j);
    biascat<<<8, 256>>>(bq, bl, bk, bv, bqlp, bkvp);

    // q scaled by QSCALE*log2e so softmax uses raw ex2
    gemm_tc<1><<<dim3(QLD/64, ROWS/128), 256, G_SMEM>>>(
        xh, xl, wqlh, wqll, bqlp, nullptr, qlh, qll, QLD, DIM, DIM, DIM, QSCALE*LOG2E, 1.0f);
    gemm_tc<1><<<dim3(KVLD/64, ROWS/128), 256, G_SMEM>>>(
        qlh + DIM, qll + DIM, wkvh, wkvl, bkvp, nullptr, kvh, kvl, KVLD, LATENT, QLD, 0, 1.0f, 1.0f);
    vtsplit<<<dim3(SEQ/32, DIM/32, BATCH), 256>>>(kvh, kvl, vth, vtl);
    attn_tc<<<dim3(SEQ/128, HEADS, BATCH), 256, A_SMEM>>>(qlh, qll, kvh, kvl, vth, vtl, ah, al);
    gemm_tc<0><<<dim3(DIM/64, ROWS/128), 256, G_SMEM>>>(
        ah, al, woh, wol, bo, out, nullptr, nullptr, DIM, DIM, DIM, 0, 1.0f, 1.0f);
}